// round 4
// baseline (speedup 1.0000x reference)
#include <cuda_runtime.h>
#include <cuda_bf16.h>
#include <cstdint>
#include <math.h>

// ---------------------------------------------------------------------------
// Round 4: HMMA bf16 hi/lo split GEMM, BK=32 / 3-stage cp.async / 3 CTAs/SM.
// ---------------------------------------------------------------------------

#define M_TOT   6272
#define CDIM    512
#define HW      196
#define BATCH   32
#define HIDN    128
#define AANCH   3
#define NELEM   (M_TOT * CDIM)
#define NLAYER  18

#define BM 128
#define BN 64
#define BK 32
#define KSTAGES 16           // 512 / 32
// stage layout: 64B rows, SW64 swizzle
#define SA_HI 0
#define SA_LO 8192
#define SB_HI 16384
#define SB_LO 20480
#define STAGE_BYTES 24576
#define NPIPE 3
#define SMEM_DYN (NPIPE * STAGE_BYTES + 128)

__device__ float g_bufA[NELEM];
__device__ float g_anc0[NELEM];
__device__ float g_anc1[NELEM];
__device__ float g_anc2[NELEM];
__device__ float g_gates[BATCH * AANCH * CDIM];
__device__ __nv_bfloat16 g_Ahi[2 * NELEM];
__device__ __nv_bfloat16 g_Alo[2 * NELEM];
__device__ __nv_bfloat16 g_Whi[NLAYER * CDIM * CDIM];  // [l][n][k]
__device__ __nv_bfloat16 g_Wlo[NLAYER * CDIM * CDIM];

// ---------------------------------------------------------------------------
__device__ __forceinline__ uint32_t sw64(uint32_t off) {
    return off ^ ((off >> 3) & 0x30);
}
__device__ __forceinline__ void cpa16(uint32_t s, const void* g) {
    asm volatile("cp.async.cg.shared.global [%0], [%1], 16;" :: "r"(s), "l"(g));
}
__device__ __forceinline__ void cpa_commit() {
    asm volatile("cp.async.commit_group;" ::: "memory");
}
__device__ __forceinline__ void cpa_wait1() {
    asm volatile("cp.async.wait_group 1;" ::: "memory");
}
__device__ __forceinline__ void ldsm_x4(uint32_t& r0, uint32_t& r1, uint32_t& r2,
                                        uint32_t& r3, uint32_t a) {
    asm volatile("ldmatrix.sync.aligned.m8n8.x4.shared.b16 {%0,%1,%2,%3}, [%4];"
                 : "=r"(r0), "=r"(r1), "=r"(r2), "=r"(r3) : "r"(a));
}
__device__ __forceinline__ void mma_bf16(float* c, const uint32_t* a, const uint32_t* b) {
    asm volatile(
        "mma.sync.aligned.m16n8k16.row.col.f32.bf16.bf16.f32 "
        "{%0,%1,%2,%3},{%4,%5,%6,%7},{%8,%9},{%0,%1,%2,%3};"
        : "+f"(c[0]), "+f"(c[1]), "+f"(c[2]), "+f"(c[3])
        : "r"(a[0]), "r"(a[1]), "r"(a[2]), "r"(a[3]), "r"(b[0]), "r"(b[1]));
}
__device__ __forceinline__ float gelu_fast(float x) {
    float u = 0.7978845608028654f * fmaf(0.044715f * x, x * x, x);
    float e = __expf(2.0f * u);
    return 0.5f * x * (1.0f + (1.0f - 2.0f / (e + 1.0f)));
}
__device__ __forceinline__ float gelu_tanh(float x) {
    float x3 = x * x * x;
    return 0.5f * x * (1.0f + tanhf(0.7978845608028654f * (x + 0.044715f * x3)));
}
__device__ __forceinline__ uint32_t pack_bf2(float a, float b) {
    __nv_bfloat162 t = __floats2bfloat162_rn(a, b);
    return *reinterpret_cast<uint32_t*>(&t);
}
__device__ __forceinline__ __nv_bfloat162 split_hi2(float a, float b, float& la, float& lb) {
    __nv_bfloat16 ha = __float2bfloat16(a);
    __nv_bfloat16 hb = __float2bfloat16(b);
    la = a - __bfloat162float(ha);
    lb = b - __bfloat162float(hb);
    __nv_bfloat162 h; h.x = ha; h.y = hb;
    return h;
}

// ---------------------------------------------------------------------------
// GEMM: 256 thr, 8 warps (4m x 2n), warp tile 32x32, 3-stage pipeline.
// ---------------------------------------------------------------------------
__global__ __launch_bounds__(256, 3)
void gemm_hmma(const __nv_bfloat16* __restrict__ aHi, const __nv_bfloat16* __restrict__ aLo,
               const __nv_bfloat16* __restrict__ bHi, const __nv_bfloat16* __restrict__ bLo,
               const float* __restrict__ bias,
               float* __restrict__ out,
               __nv_bfloat16* __restrict__ nHi, __nv_bfloat16* __restrict__ nLo) {
    extern __shared__ char smraw[];
    const uint32_t sb = (uint32_t)__cvta_generic_to_shared(smraw);

    const int t = threadIdx.x;
    const int lane = t & 31;
    const int w = t >> 5;
    const int wm = (w >> 1) * 32;
    const int wn = (w & 1) * 32;
    const int bm = blockIdx.x * BM;
    const int bn = blockIdx.y * BN;

    const int lrow = t >> 2;        // 0..63
    const int lchk = t & 3;         // 16B chunk in 64B row

    auto load_stage = [&](int s, int buf) {
        const int k0 = s * BK;
        const uint32_t stg = sb + (uint32_t)buf * STAGE_BYTES;
        const uint32_t so0 = sw64((uint32_t)lrow * 64 + lchk * 16);
        const uint32_t so1 = sw64((uint32_t)(lrow + 64) * 64 + lchk * 16);
        const size_t ga0 = (size_t)(bm + lrow) * CDIM + k0 + lchk * 8;
        const size_t ga1 = ga0 + (size_t)64 * CDIM;
        cpa16(stg + SA_HI + so0, aHi + ga0);
        cpa16(stg + SA_HI + so1, aHi + ga1);
        cpa16(stg + SA_LO + so0, aLo + ga0);
        cpa16(stg + SA_LO + so1, aLo + ga1);
        const size_t gb = (size_t)(bn + lrow) * CDIM + k0 + lchk * 8;
        cpa16(stg + SB_HI + so0, bHi + gb);
        cpa16(stg + SB_LO + so0, bLo + gb);
    };

    // ldmatrix base offsets (unswizzled)
    uint32_t a_off[2];
#pragma unroll
    for (int mi = 0; mi < 2; ++mi)
        a_off[mi] = (uint32_t)(wm + mi * 16 + (lane & 15)) * 64 + ((lane >> 4) & 1) * 16;
    uint32_t b_off[2];
#pragma unroll
    for (int g = 0; g < 2; ++g)
        b_off[g] = (uint32_t)(wn + g * 16 + ((lane >> 4) & 1) * 8 + (lane & 7)) * 64 +
                   ((lane >> 3) & 1) * 16;

    float acc[2][4][4];
#pragma unroll
    for (int mi = 0; mi < 2; ++mi)
#pragma unroll
        for (int nf = 0; nf < 4; ++nf)
#pragma unroll
            for (int r = 0; r < 4; ++r) acc[mi][nf][r] = 0.0f;

    load_stage(0, 0); cpa_commit();
    load_stage(1, 1); cpa_commit();

    int buf = 0, nbuf = 2;
#pragma unroll 1
    for (int s = 0; s < KSTAGES; ++s) {
        cpa_wait1();
        __syncthreads();
        if (s + 2 < KSTAGES) {
            load_stage(s + 2, nbuf);
            if (++nbuf == NPIPE) nbuf = 0;
        }
        cpa_commit();
        const uint32_t stg = sb + (uint32_t)buf * STAGE_BYTES;
        if (++buf == NPIPE) buf = 0;

#pragma unroll
        for (int kk = 0; kk < 2; ++kk) {
            const uint32_t kb = kk * 32;
            uint32_t ah[2][4], al[2][4], bb[2][4];
            // hi*hi
#pragma unroll
            for (int mi = 0; mi < 2; ++mi)
                ldsm_x4(ah[mi][0], ah[mi][1], ah[mi][2], ah[mi][3],
                        stg + SA_HI + sw64(a_off[mi] + kb));
#pragma unroll
            for (int g = 0; g < 2; ++g)
                ldsm_x4(bb[g][0], bb[g][1], bb[g][2], bb[g][3],
                        stg + SB_HI + sw64(b_off[g] + kb));
#pragma unroll
            for (int mi = 0; mi < 2; ++mi)
#pragma unroll
                for (int nf = 0; nf < 4; ++nf)
                    mma_bf16(acc[mi][nf], ah[mi], &bb[nf >> 1][(nf & 1) * 2]);
            // lo*hi (uses bb then retires it)
#pragma unroll
            for (int mi = 0; mi < 2; ++mi)
                ldsm_x4(al[mi][0], al[mi][1], al[mi][2], al[mi][3],
                        stg + SA_LO + sw64(a_off[mi] + kb));
#pragma unroll
            for (int mi = 0; mi < 2; ++mi)
#pragma unroll
                for (int nf = 0; nf < 4; ++nf)
                    mma_bf16(acc[mi][nf], al[mi], &bb[nf >> 1][(nf & 1) * 2]);
            // hi*lo (reload bb with lo)
#pragma unroll
            for (int g = 0; g < 2; ++g)
                ldsm_x4(bb[g][0], bb[g][1], bb[g][2], bb[g][3],
                        stg + SB_LO + sw64(b_off[g] + kb));
#pragma unroll
            for (int mi = 0; mi < 2; ++mi)
#pragma unroll
                for (int nf = 0; nf < 4; ++nf)
                    mma_bf16(acc[mi][nf], ah[mi], &bb[nf >> 1][(nf & 1) * 2]);
        }
    }

    // epilogue
    const int r0 = bm + wm + (lane >> 2);
    const int cbase = bn + wn + (lane & 3) * 2;
#pragma unroll
    for (int mi = 0; mi < 2; ++mi) {
#pragma unroll
        for (int nf = 0; nf < 4; ++nf) {
            const int c = cbase + nf * 8;
            const float2 bv = *reinterpret_cast<const float2*>(&bias[c]);
            const int ra = r0 + mi * 16;
            const int rb = ra + 8;
            float v0 = gelu_fast(acc[mi][nf][0] + bv.x);
            float v1 = gelu_fast(acc[mi][nf][1] + bv.y);
            float v2 = gelu_fast(acc[mi][nf][2] + bv.x);
            float v3 = gelu_fast(acc[mi][nf][3] + bv.y);
            if (out) {
                *reinterpret_cast<float2*>(&out[(size_t)ra * CDIM + c]) = make_float2(v0, v1);
                *reinterpret_cast<float2*>(&out[(size_t)rb * CDIM + c]) = make_float2(v2, v3);
            }
            if (nHi) {
                float l0, l1, l2, l3;
                __nv_bfloat162 h01 = split_hi2(v0, v1, l0, l1);
                __nv_bfloat162 h23 = split_hi2(v2, v3, l2, l3);
                *reinterpret_cast<__nv_bfloat162*>(&nHi[(size_t)ra * CDIM + c]) = h01;
                *reinterpret_cast<__nv_bfloat162*>(&nHi[(size_t)rb * CDIM + c]) = h23;
                *reinterpret_cast<uint32_t*>(&nLo[(size_t)ra * CDIM + c]) = pack_bf2(l0, l1);
                *reinterpret_cast<uint32_t*>(&nLo[(size_t)rb * CDIM + c]) = pack_bf2(l2, l3);
            }
        }
    }
}

// ---------------------------------------------------------------------------
__global__ void convert_x(const float* __restrict__ x,
                          __nv_bfloat16* __restrict__ hi, __nv_bfloat16* __restrict__ lo) {
    int i = blockIdx.x * blockDim.x + threadIdx.x;
    if (i >= NELEM / 4) return;
    float4 v = reinterpret_cast<const float4*>(x)[i];
    float l0, l1, l2, l3;
    __nv_bfloat162 h01 = split_hi2(v.x, v.y, l0, l1);
    __nv_bfloat162 h23 = split_hi2(v.z, v.w, l2, l3);
    reinterpret_cast<uint2*>(hi)[i] = make_uint2(*reinterpret_cast<uint32_t*>(&h01),
                                                 *reinterpret_cast<uint32_t*>(&h23));
    reinterpret_cast<uint2*>(lo)[i] = make_uint2(pack_bf2(l0, l1), pack_bf2(l2, l3));
}

__global__ void convert_w(const float* __restrict__ W,
                          __nv_bfloat16* __restrict__ whi, __nv_bfloat16* __restrict__ wlo) {
    __shared__ float tile[32][33];
    const int l = blockIdx.z;
    const int kt = blockIdx.y * 32;
    const int nt = blockIdx.x * 32;
    const int tx = threadIdx.x, ty = threadIdx.y;
    const size_t lb = (size_t)l * CDIM * CDIM;
#pragma unroll
    for (int q = 0; q < 4; ++q)
        tile[ty + 8 * q][tx] = W[lb + (size_t)(kt + ty + 8 * q) * CDIM + nt + tx];
    __syncthreads();
#pragma unroll
    for (int q = 0; q < 4; ++q) {
        float v = tile[tx][ty + 8 * q];
        __nv_bfloat16 h = __float2bfloat16(v);
        size_t idx = lb + (size_t)(nt + ty + 8 * q) * CDIM + kt + tx;
        whi[idx] = h;
        wlo[idx] = __float2bfloat16(v - __bfloat162float(h));
    }
}

// ---------------------------------------------------------------------------
// Fused pool + router MLP: one block per batch elem.
// ---------------------------------------------------------------------------
__global__ __launch_bounds__(128)
void gate_kernel(const float* __restrict__ act,
                 const float* __restrict__ fc1w, const float* __restrict__ fc1b,
                 const float* __restrict__ fc2w, const float* __restrict__ fc2b,
                 float* __restrict__ gates) {
    __shared__ float ps[CDIM];
    __shared__ float hs[HIDN];
    __shared__ float lg[AANCH * CDIM];
    const int b = blockIdx.x;
    const int t = threadIdx.x;

    // pool: each thread owns 4 channels (float4)
    {
        const float* p = act + (size_t)b * HW * CDIM + t * 4;
        float4 s = make_float4(0.f, 0.f, 0.f, 0.f);
#pragma unroll 4
        for (int r = 0; r < HW; ++r) {
            float4 v = *reinterpret_cast<const float4*>(p + (size_t)r * CDIM);
            s.x += v.x; s.y += v.y; s.z += v.z; s.w += v.w;
        }
        const float inv = 1.0f / (float)HW;
        *reinterpret_cast<float4*>(&ps[t * 4]) =
            make_float4(s.x * inv, s.y * inv, s.z * inv, s.w * inv);
    }
    __syncthreads();

    float acc = fc1b[t];
#pragma unroll 8
    for (int k = 0; k < CDIM; ++k)
        acc = fmaf(ps[k], fc1w[k * HIDN + t], acc);
    hs[t] = gelu_tanh(acc);
    __syncthreads();

    for (int j = t; j < AANCH * CDIM; j += 128) {
        float a2 = fc2b[j];
#pragma unroll 8
        for (int k = 0; k < HIDN; ++k)
            a2 = fmaf(hs[k], fc2w[k * (AANCH * CDIM) + j], a2);
        lg[j] = a2;
    }
    __syncthreads();

    for (int c = t; c < CDIM; c += 128) {
        float l0 = lg[c], l1 = lg[CDIM + c], l2 = lg[2 * CDIM + c];
        float m = fmaxf(l0, fmaxf(l1, l2));
        float e0 = expf(l0 - m), e1 = expf(l1 - m), e2 = expf(l2 - m);
        float inv = 1.0f / (e0 + e1 + e2);
        gates[b * AANCH * CDIM + c]            = e0 * inv;
        gates[b * AANCH * CDIM + CDIM + c]     = e1 * inv;
        gates[b * AANCH * CDIM + 2 * CDIM + c] = e2 * inv;
    }
}

__global__ void route_kernel(float* __restrict__ nx,
                             const float* __restrict__ a0,
                             const float* __restrict__ a1,
                             const float* __restrict__ a2,
                             const float* __restrict__ gates,
                             const float* __restrict__ gammas, int tgt,
                             __nv_bfloat16* __restrict__ nhi,
                             __nv_bfloat16* __restrict__ nlo) {
    const int i = blockIdx.x * blockDim.x + threadIdx.x;
    if (i >= NELEM / 4) return;
    const float gamma = gammas[tgt];
    const int per_b = HW * CDIM / 4;
    const int b = i / per_b;
    const int c4 = i & (CDIM / 4 - 1);

    const float4 g0 = *reinterpret_cast<const float4*>(&gates[b * AANCH * CDIM + c4 * 4]);
    const float4 g1 = *reinterpret_cast<const float4*>(&gates[b * AANCH * CDIM + CDIM + c4 * 4]);
    const float4 g2 = *reinterpret_cast<const float4*>(&gates[b * AANCH * CDIM + 2 * CDIM + c4 * 4]);

    float4 v  = reinterpret_cast<float4*>(nx)[i];
    float4 x0 = reinterpret_cast<const float4*>(a0)[i];
    float4 x1 = reinterpret_cast<const float4*>(a1)[i];
    float4 x2 = reinterpret_cast<const float4*>(a2)[i];

    v.x += gamma * (g0.x * x0.x + g1.x * x1.x + g2.x * x2.x);
    v.y += gamma * (g0.y * x0.y + g1.y * x1.y + g2.y * x2.y);
    v.z += gamma * (g0.z * x0.z + g1.z * x1.z + g2.z * x2.z);
    v.w += gamma * (g0.w * x0.w + g1.w * x1.w + g2.w * x2.w);

    reinterpret_cast<float4*>(nx)[i] = v;

    if (nhi) {
        float l0, l1, l2, l3;
        __nv_bfloat162 h01 = split_hi2(v.x, v.y, l0, l1);
        __nv_bfloat162 h23 = split_hi2(v.z, v.w, l2, l3);
        reinterpret_cast<uint2*>(nhi)[i] = make_uint2(*reinterpret_cast<uint32_t*>(&h01),
                                                      *reinterpret_cast<uint32_t*>(&h23));
        reinterpret_cast<uint2*>(nlo)[i] = make_uint2(pack_bf2(l0, l1), pack_bf2(l2, l3));
    }
}

// ---------------------------------------------------------------------------
extern "C" void kernel_launch(void* const* d_in, const int* in_sizes, int n_in,
                              void* d_out, int out_size) {
    const float* x   = (const float*)d_in[0];
    const float* bw  = (const float*)d_in[1];
    const float* bb  = (const float*)d_in[2];
    const float* f1w = (const float*)d_in[3];
    const float* f1b = (const float*)d_in[4];
    const float* f2w = (const float*)d_in[5];
    const float* f2b = (const float*)d_in[6];
    const float* gam = (const float*)d_in[7];

    float *bufA, *anc0, *anc1, *anc2, *gates;
    __nv_bfloat16 *ahi, *alo, *whi, *wlo;
    cudaGetSymbolAddress((void**)&bufA,  g_bufA);
    cudaGetSymbolAddress((void**)&anc0,  g_anc0);
    cudaGetSymbolAddress((void**)&anc1,  g_anc1);
    cudaGetSymbolAddress((void**)&anc2,  g_anc2);
    cudaGetSymbolAddress((void**)&gates, g_gates);
    cudaGetSymbolAddress((void**)&ahi,   g_Ahi);
    cudaGetSymbolAddress((void**)&alo,   g_Alo);
    cudaGetSymbolAddress((void**)&whi,   g_Whi);
    cudaGetSymbolAddress((void**)&wlo,   g_Wlo);

    cudaFuncSetAttribute(gemm_hmma, cudaFuncAttributeMaxDynamicSharedMemorySize, SMEM_DYN);

    convert_w<<<dim3(CDIM / 32, CDIM / 32, NLAYER), dim3(32, 8)>>>(bw, whi, wlo);
    convert_x<<<(NELEM / 4 + 255) / 256, 256>>>(x, ahi, alo);

    const dim3 gemm_grid(M_TOT / BM, CDIM / BN);   // 49 x 8
    int tcount = 0;
    for (int i = 0; i < NLAYER; ++i) {
        float* dst;
        if      (i == 1)  dst = anc0;
        else if (i == 4)  dst = anc1;
        else if (i == 9)  dst = anc2;
        else if (i == 17) dst = (float*)d_out;
        else if (i == 11 || i == 14) dst = bufA;
        else              dst = nullptr;

        const int inS  = i & 1;
        const int outS = (i + 1) & 1;
        const bool last = (i == 17);
        __nv_bfloat16* nhi = last ? nullptr : ahi + (size_t)outS * NELEM;
        __nv_bfloat16* nlo = last ? nullptr : alo + (size_t)outS * NELEM;

        gemm_hmma<<<gemm_grid, 256, SMEM_DYN>>>(
            ahi + (size_t)inS * NELEM, alo + (size_t)inS * NELEM,
            whi + (size_t)i * CDIM * CDIM, wlo + (size_t)i * CDIM * CDIM,
            bb + (size_t)i * CDIM, dst, nhi, nlo);

        if (i == 11 || i == 14 || i == 17) {
            const int tt = tcount++;
            gate_kernel<<<BATCH, 128>>>(dst,
                                        f1w + (size_t)tt * CDIM * HIDN,
                                        f1b + (size_t)tt * HIDN,
                                        f2w + (size_t)tt * HIDN * AANCH * CDIM,
                                        f2b + (size_t)tt * AANCH * CDIM,
                                        gates);
            route_kernel<<<(NELEM / 4 + 255) / 256, 256>>>(dst, anc0, anc1, anc2,
                                                           gates, gam, tt, nhi, nlo);
        }
    }
}